// round 7
// baseline (speedup 1.0000x reference)
#include <cuda_runtime.h>
#include <cuda_fp16.h>

// QuantizedBatchNorm3d: x [8,64,32,64,64] fp32, weight[64], bias[64] -> y same shape.
// fake_quant(exp=5, sig=10, RNE) == IEEE fp16 round-trip for all reachable values.
//
// R7: reduce geometry reverted to R5's measured-best (2048 blocks x 256 thr x
// 32 float4/thread @ 6.59 TB/s); finalize stays FUSED via last-block atomic
// (deletes one kernel node). Apply identical to R5/R6 (mixed-stream ceiling).

#define NB        8
#define NC        64
#define SPATIAL   (32*64*64)            // 2^17 elements per (n,c) slice
#define CPC       (NB*SPATIAL)          // 2^20 elements per channel
#define RBLOCKS   2048                  // reduce blocks, 8192 float4 each
#define RTHREADS  256
#define PARTS     32                    // partials per channel (2048/64)

#define ABLOCKS   8192                  // apply blocks
#define ACHUNK    2048                  // float4 per apply block (2048 | 32768)

__device__ float    g_psum[NC * PARTS];
__device__ float    g_psq [NC * PARTS];
__device__ float4   g_params[NC];       // {mean_q, inv_std, w_q, b_q}
__device__ unsigned g_count;            // zero-init; reset by last block each run

__device__ __forceinline__ float fq1(float v) {
    return __half2float(__float2half_rn(v));
}
__device__ __forceinline__ float2 fq2(float a, float b) {
    __half2 h = __floats2half2_rn(a, b);
    return __half22float2(h);
}

// ---- Pass 1 (fused): per-channel sum/sumsq of fq(x) + last-block finalize ----
// Block b covers float4 [b*8192, (b+1)*8192). A (n,c) slice is 32768 float4,
// so c = (b>>2)&63, part = n*4 + (b&3) with n = b>>8.
__global__ void __launch_bounds__(RTHREADS) qbn_reduce(const float* __restrict__ x,
                                                       const float* __restrict__ weight,
                                                       const float* __restrict__ bias) {
    const int b   = blockIdx.x;
    const int tid = threadIdx.x;
    const float4* p = reinterpret_cast<const float4*>(x) + (size_t)b * 8192;

    float s = 0.f, sq = 0.f;
    #pragma unroll
    for (int i = 0; i < 32; i++) {
        float4 v = p[i * RTHREADS + tid];
        float2 a  = fq2(v.x, v.y);
        float2 c2 = fq2(v.z, v.w);
        s  += (a.x + a.y) + (c2.x + c2.y);
        sq += a.x*a.x + a.y*a.y + c2.x*c2.x + c2.y*c2.y;
    }

    #pragma unroll
    for (int o = 16; o > 0; o >>= 1) {
        s  += __shfl_down_sync(0xffffffffu, s,  o);
        sq += __shfl_down_sync(0xffffffffu, sq, o);
    }
    __shared__ float sh_s[RTHREADS / 32], sh_q[RTHREADS / 32];
    __shared__ bool  sh_last;
    const int lane = tid & 31, w = tid >> 5;
    if (lane == 0) { sh_s[w] = s; sh_q[w] = sq; }
    __syncthreads();
    if (w == 0) {
        s  = (lane < RTHREADS / 32) ? sh_s[lane] : 0.f;
        sq = (lane < RTHREADS / 32) ? sh_q[lane] : 0.f;
        #pragma unroll
        for (int o = 4; o > 0; o >>= 1) {
            s  += __shfl_down_sync(0xffffffffu, s,  o);
            sq += __shfl_down_sync(0xffffffffu, sq, o);
        }
        if (lane == 0) {
            const int c    = (b >> 2) & (NC - 1);
            const int part = ((b >> 8) << 2) | (b & 3);   // n*4 + piece, 0..31
            g_psum[c * PARTS + part] = s;
            g_psq [c * PARTS + part] = sq;
            __threadfence();
            sh_last = (atomicAdd(&g_count, 1u) == RBLOCKS - 1);
        }
    }
    __syncthreads();

    if (sh_last) {
        if (tid < NC) {
            const int c = tid;
            float ss = 0.f, qq = 0.f;
            #pragma unroll
            for (int i = 0; i < PARTS; i++) {
                ss += g_psum[c * PARTS + i];
                qq += g_psq [c * PARTS + i];
            }
            const float inv_n = 1.0f / (float)CPC;
            float mean = ss * inv_n;
            float var  = qq * inv_n - mean * mean;
            float mean_q  = fq1(mean);
            float var_q   = fq1(var);
            float inv_std = 1.0f / sqrtf(var_q + 1e-5f);
            float w_q     = fq1(weight[c]);
            float b_q     = fq1(bias[c]);
            g_params[c] = make_float4(mean_q, inv_std, w_q, b_q);
        }
        if (tid == 0) g_count = 0;      // reset for next graph replay
    }
}

// -------- Pass 2: normalize + final quant. 8 float4/thread, loads batched --------
__global__ void __launch_bounds__(RTHREADS) qbn_apply(const float* __restrict__ x,
                                                      float* __restrict__ out) {
    const int cc   = (ABLOCKS - 1) - blockIdx.x;
    const int tid  = threadIdx.x;
    const size_t base = (size_t)cc * ACHUNK;

    // Channel constant for the whole block (ACHUNK divides the 32768-float4 slice).
    const int c = (int)((base >> 15) & (NC - 1));
    const float4 p = g_params[c];               // {mean, inv_std, w, b}

    const float4* xin = reinterpret_cast<const float4*>(x) + base;
    float4*       yo  = reinterpret_cast<float4*>(out) + base;

    float4 v[8];
    #pragma unroll
    for (int k = 0; k < 8; k++)
        v[k] = __ldcs(xin + tid + k * RTHREADS);

    #pragma unroll
    for (int k = 0; k < 8; k++) {
        float2 a = fq2(v[k].x, v[k].y);
        float2 b = fq2(v[k].z, v[k].w);
        float y0 = fmaf(p.z, (a.x - p.x) * p.y, p.w);
        float y1 = fmaf(p.z, (a.y - p.x) * p.y, p.w);
        float y2 = fmaf(p.z, (b.x - p.x) * p.y, p.w);
        float y3 = fmaf(p.z, (b.y - p.x) * p.y, p.w);
        float2 q0 = fq2(y0, y1);
        float2 q1 = fq2(y2, y3);
        __stcs(yo + tid + k * RTHREADS, make_float4(q0.x, q0.y, q1.x, q1.y));
    }
}

extern "C" void kernel_launch(void* const* d_in, const int* in_sizes, int n_in,
                              void* d_out, int out_size) {
    const float* x      = (const float*)d_in[0];
    const float* weight = (const float*)d_in[1];
    const float* bias   = (const float*)d_in[2];
    float* out = (float*)d_out;

    qbn_reduce<<<RBLOCKS, RTHREADS>>>(x, weight, bias);
    qbn_apply <<<ABLOCKS, RTHREADS>>>(x, out);
}

// round 8
// speedup vs baseline: 1.0067x; 1.0067x over previous
#include <cuda_runtime.h>
#include <cuda_fp16.h>

// QuantizedBatchNorm3d: x [8,64,32,64,64] fp32, weight[64], bias[64] -> y same shape.
// fake_quant(exp=5, sig=10, RNE) == IEEE fp16 round-trip for all reachable values.
//
// R8: no finalize stage at all. Reduce (R5's measured-best geometry, no atomics,
// no fences) writes 32 partials/channel. Each apply block is chunk-aligned to a
// single channel, so its warp 0 reduces that channel's 32 partials (256B, L2-hot)
// and computes params in the prologue, overlapped with the front-batched x loads.

#define NB        8
#define NC        64
#define SPATIAL   (32*64*64)            // 2^17 elements per (n,c) slice
#define CPC       (NB*SPATIAL)          // 2^20 elements per channel
#define RBLOCKS   2048                  // reduce blocks, 8192 float4 each
#define RTHREADS  256
#define PARTS     32                    // partials per channel (2048/64)

#define ABLOCKS   8192                  // apply blocks
#define ACHUNK    2048                  // float4 per apply block (2048 | 32768)

__device__ float g_psum[NC * PARTS];
__device__ float g_psq [NC * PARTS];

__device__ __forceinline__ float fq1(float v) {
    return __half2float(__float2half_rn(v));
}
__device__ __forceinline__ float2 fq2(float a, float b) {
    __half2 h = __floats2half2_rn(a, b);
    return __half22float2(h);
}

// ---------- Pass 1: per-channel sum/sumsq of fq(x), contiguous-chunk blocks ----------
// Block b covers float4 [b*8192, (b+1)*8192). A (n,c) slice is 32768 float4,
// so c = (b>>2)&63, part = n*4 + (b&3) with n = b>>8.
__global__ void __launch_bounds__(RTHREADS) qbn_reduce(const float* __restrict__ x) {
    const int b   = blockIdx.x;
    const int tid = threadIdx.x;
    const float4* p = reinterpret_cast<const float4*>(x) + (size_t)b * 8192;

    float s = 0.f, sq = 0.f;
    #pragma unroll
    for (int i = 0; i < 32; i++) {
        float4 v = p[i * RTHREADS + tid];
        float2 a  = fq2(v.x, v.y);
        float2 c2 = fq2(v.z, v.w);
        s  += (a.x + a.y) + (c2.x + c2.y);
        sq += a.x*a.x + a.y*a.y + c2.x*c2.x + c2.y*c2.y;
    }

    #pragma unroll
    for (int o = 16; o > 0; o >>= 1) {
        s  += __shfl_down_sync(0xffffffffu, s,  o);
        sq += __shfl_down_sync(0xffffffffu, sq, o);
    }
    __shared__ float sh_s[RTHREADS / 32], sh_q[RTHREADS / 32];
    const int lane = tid & 31, w = tid >> 5;
    if (lane == 0) { sh_s[w] = s; sh_q[w] = sq; }
    __syncthreads();
    if (w == 0) {
        s  = (lane < RTHREADS / 32) ? sh_s[lane] : 0.f;
        sq = (lane < RTHREADS / 32) ? sh_q[lane] : 0.f;
        #pragma unroll
        for (int o = 4; o > 0; o >>= 1) {
            s  += __shfl_down_sync(0xffffffffu, s,  o);
            sq += __shfl_down_sync(0xffffffffu, sq, o);
        }
        if (lane == 0) {
            const int c    = (b >> 2) & (NC - 1);
            const int part = ((b >> 8) << 2) | (b & 3);   // n*4 + piece, 0..31
            g_psum[c * PARTS + part] = s;
            g_psq [c * PARTS + part] = sq;
        }
    }
}

// -------- Pass 2: per-block param finalize (one channel) + normalize + quant --------
__global__ void __launch_bounds__(RTHREADS) qbn_apply(const float* __restrict__ x,
                                                      const float* __restrict__ weight,
                                                      const float* __restrict__ bias,
                                                      float* __restrict__ out) {
    const int tid  = threadIdx.x;
    const size_t base = (size_t)blockIdx.x * ACHUNK;

    // Channel constant for the whole block (ACHUNK divides the 32768-float4 slice).
    const int c = (int)((base >> 15) & (NC - 1));

    const float4* xin = reinterpret_cast<const float4*>(x) + base;
    float4*       yo  = reinterpret_cast<float4*>(out) + base;

    // Issue the x loads FIRST (no dependence on params): MLP = 8 per thread.
    float4 v[8];
    #pragma unroll
    for (int k = 0; k < 8; k++)
        v[k] = __ldcs(xin + tid + k * RTHREADS);

    // Warp 0 finalizes this block's channel params while loads are in flight.
    __shared__ float4 sp;
    if (tid < 32) {
        float ss = g_psum[c * PARTS + tid];
        float qq = g_psq [c * PARTS + tid];
        #pragma unroll
        for (int o = 16; o > 0; o >>= 1) {
            ss += __shfl_down_sync(0xffffffffu, ss, o);
            qq += __shfl_down_sync(0xffffffffu, qq, o);
        }
        if (tid == 0) {
            const float inv_n = 1.0f / (float)CPC;
            float mean = ss * inv_n;
            float var  = qq * inv_n - mean * mean;
            float mean_q  = fq1(mean);
            float var_q   = fq1(var);
            float inv_std = 1.0f / sqrtf(var_q + 1e-5f);
            float w_q     = fq1(weight[c]);
            float b_q     = fq1(bias[c]);
            sp = make_float4(mean_q, inv_std, w_q, b_q);
        }
    }
    __syncthreads();
    const float4 p = sp;                 // {mean, inv_std, w, b}

    #pragma unroll
    for (int k = 0; k < 8; k++) {
        float2 a = fq2(v[k].x, v[k].y);
        float2 b = fq2(v[k].z, v[k].w);
        float y0 = fmaf(p.z, (a.x - p.x) * p.y, p.w);
        float y1 = fmaf(p.z, (a.y - p.x) * p.y, p.w);
        float y2 = fmaf(p.z, (b.x - p.x) * p.y, p.w);
        float y3 = fmaf(p.z, (b.y - p.x) * p.y, p.w);
        float2 q0 = fq2(y0, y1);
        float2 q1 = fq2(y2, y3);
        __stcs(yo + tid + k * RTHREADS, make_float4(q0.x, q0.y, q1.x, q1.y));
    }
}

extern "C" void kernel_launch(void* const* d_in, const int* in_sizes, int n_in,
                              void* d_out, int out_size) {
    const float* x      = (const float*)d_in[0];
    const float* weight = (const float*)d_in[1];
    const float* bias   = (const float*)d_in[2];
    float* out = (float*)d_out;

    qbn_reduce<<<RBLOCKS, RTHREADS>>>(x);
    qbn_apply <<<ABLOCKS, RTHREADS>>>(x, weight, bias, out);
}

// round 9
// speedup vs baseline: 1.0155x; 1.0088x over previous
#include <cuda_runtime.h>
#include <cuda_fp16.h>

// QuantizedBatchNorm3d: x [8,64,32,64,64] fp32, weight[64], bias[64] -> y same shape.
// fake_quant(exp=5, sig=10, RNE) == IEEE fp16 round-trip for all reachable values.
//
// R9: R8's two-kernel structure + PDL overlap. Apply is launched with
// programmatic stream serialization; reduce triggers launch_dependents per-CTA
// right after storing its partials, so apply's CTAs launch and front-batch
// their x loads while reduce's tail drains. Apply waits (griddepcontrol.wait)
// only before reading the partials. Degrades to plain serialization if late.

#define NB        8
#define NC        64
#define SPATIAL   (32*64*64)            // 2^17 elements per (n,c) slice
#define CPC       (NB*SPATIAL)          // 2^20 elements per channel
#define RBLOCKS   2048                  // reduce blocks, 8192 float4 each
#define RTHREADS  256
#define PARTS     32                    // partials per channel (2048/64)

#define ABLOCKS   8192                  // apply blocks
#define ACHUNK    2048                  // float4 per apply block (2048 | 32768)

__device__ float g_psum[NC * PARTS];
__device__ float g_psq [NC * PARTS];

__device__ __forceinline__ float fq1(float v) {
    return __half2float(__float2half_rn(v));
}
__device__ __forceinline__ float2 fq2(float a, float b) {
    __half2 h = __floats2half2_rn(a, b);
    return __half22float2(h);
}

// ---------- Pass 1: per-channel sum/sumsq of fq(x), contiguous-chunk blocks ----------
__global__ void __launch_bounds__(RTHREADS) qbn_reduce(const float* __restrict__ x) {
    const int b   = blockIdx.x;
    const int tid = threadIdx.x;
    const float4* p = reinterpret_cast<const float4*>(x) + (size_t)b * 8192;

    float s = 0.f, sq = 0.f;
    #pragma unroll
    for (int i = 0; i < 32; i++) {
        float4 v = p[i * RTHREADS + tid];
        float2 a  = fq2(v.x, v.y);
        float2 c2 = fq2(v.z, v.w);
        s  += (a.x + a.y) + (c2.x + c2.y);
        sq += a.x*a.x + a.y*a.y + c2.x*c2.x + c2.y*c2.y;
    }

    #pragma unroll
    for (int o = 16; o > 0; o >>= 1) {
        s  += __shfl_down_sync(0xffffffffu, s,  o);
        sq += __shfl_down_sync(0xffffffffu, sq, o);
    }
    __shared__ float sh_s[RTHREADS / 32], sh_q[RTHREADS / 32];
    const int lane = tid & 31, w = tid >> 5;
    if (lane == 0) { sh_s[w] = s; sh_q[w] = sq; }
    __syncthreads();
    if (w == 0) {
        s  = (lane < RTHREADS / 32) ? sh_s[lane] : 0.f;
        sq = (lane < RTHREADS / 32) ? sh_q[lane] : 0.f;
        #pragma unroll
        for (int o = 4; o > 0; o >>= 1) {
            s  += __shfl_down_sync(0xffffffffu, s,  o);
            sq += __shfl_down_sync(0xffffffffu, sq, o);
        }
        if (lane == 0) {
            const int c    = (b >> 2) & (NC - 1);
            const int part = ((b >> 8) << 2) | (b & 3);   // n*4 + piece, 0..31
            g_psum[c * PARTS + part] = s;
            g_psq [c * PARTS + part] = sq;
            // Partials stored (same thread, program order) -> let dependents go.
            asm volatile("griddepcontrol.launch_dependents;" ::: "memory");
        }
    }
}

// -------- Pass 2: per-block param finalize (one channel) + normalize + quant --------
__global__ void __launch_bounds__(RTHREADS) qbn_apply(const float* __restrict__ x,
                                                      const float* __restrict__ weight,
                                                      const float* __restrict__ bias,
                                                      float* __restrict__ out) {
    const int tid  = threadIdx.x;
    const size_t base = (size_t)blockIdx.x * ACHUNK;

    // Channel constant for the whole block (ACHUNK divides the 32768-float4 slice).
    const int c = (int)((base >> 15) & (NC - 1));

    const float4* xin = reinterpret_cast<const float4*>(x) + base;
    float4*       yo  = reinterpret_cast<float4*>(out) + base;

    // Issue the x loads FIRST (input-only, no dependence on reduce): MLP = 8.
    float4 v[8];
    #pragma unroll
    for (int k = 0; k < 8; k++)
        v[k] = __ldcs(xin + tid + k * RTHREADS);

    // Now wait for the reduce grid's partials to be visible.
    asm volatile("griddepcontrol.wait;" ::: "memory");

    // Warp 0 finalizes this block's channel params.
    __shared__ float4 sp;
    if (tid < 32) {
        float ss = g_psum[c * PARTS + tid];
        float qq = g_psq [c * PARTS + tid];
        #pragma unroll
        for (int o = 16; o > 0; o >>= 1) {
            ss += __shfl_down_sync(0xffffffffu, ss, o);
            qq += __shfl_down_sync(0xffffffffu, qq, o);
        }
        if (tid == 0) {
            const float inv_n = 1.0f / (float)CPC;
            float mean = ss * inv_n;
            float var  = qq * inv_n - mean * mean;
            float mean_q  = fq1(mean);
            float var_q   = fq1(var);
            float inv_std = 1.0f / sqrtf(var_q + 1e-5f);
            float w_q     = fq1(weight[c]);
            float b_q     = fq1(bias[c]);
            sp = make_float4(mean_q, inv_std, w_q, b_q);
        }
    }
    __syncthreads();
    const float4 p = sp;                 // {mean, inv_std, w, b}

    #pragma unroll
    for (int k = 0; k < 8; k++) {
        float2 a = fq2(v[k].x, v[k].y);
        float2 b = fq2(v[k].z, v[k].w);
        float y0 = fmaf(p.z, (a.x - p.x) * p.y, p.w);
        float y1 = fmaf(p.z, (a.y - p.x) * p.y, p.w);
        float y2 = fmaf(p.z, (b.x - p.x) * p.y, p.w);
        float y3 = fmaf(p.z, (b.y - p.x) * p.y, p.w);
        float2 q0 = fq2(y0, y1);
        float2 q1 = fq2(y2, y3);
        __stcs(yo + tid + k * RTHREADS, make_float4(q0.x, q0.y, q1.x, q1.y));
    }
}

extern "C" void kernel_launch(void* const* d_in, const int* in_sizes, int n_in,
                              void* d_out, int out_size) {
    const float* x      = (const float*)d_in[0];
    const float* weight = (const float*)d_in[1];
    const float* bias   = (const float*)d_in[2];
    float* out = (float*)d_out;

    qbn_reduce<<<RBLOCKS, RTHREADS>>>(x);

    // Apply launched with Programmatic Dependent Launch: it may begin (and
    // front-batch its x loads) while reduce drains; griddepcontrol.wait gates
    // the partial-sum reads.
    cudaLaunchConfig_t cfg = {};
    cfg.gridDim        = dim3(ABLOCKS);
    cfg.blockDim       = dim3(RTHREADS);
    cfg.dynamicSmemBytes = 0;
    cfg.stream         = 0;
    cudaLaunchAttribute attrs[1];
    attrs[0].id = cudaLaunchAttributeProgrammaticStreamSerialization;
    attrs[0].val.programmaticStreamSerializationAllowed = 1;
    cfg.attrs    = attrs;
    cfg.numAttrs = 1;
    cudaLaunchKernelEx(&cfg, qbn_apply, x, weight, bias, out);
}